// round 10
// baseline (speedup 1.0000x reference)
#include <cuda_runtime.h>
#include <mma.h>
#include <cstddef>
#include <cstdint>

using namespace nvcuda;

#define BB 64
#define TT 512
#define DD 512
#define HH 768
#define NG 3072
#define MMROWS (BB * TT)
#define NCTA 96
#define NCTA_DIR 48

#define WS_LD 66                 // 768 x 66 floats = 202752 B (66%32=2: conflict-free bf)
#define HS_LDW 36                // stage row: 36 floats = 144 B (16B-aligned)
#define GS_LD 68
#define HS_OFF 202752
#define STAGE_B 9216             // 64 * 36 * 4
#define TAILOFF 230400           // bias
#define SMEM_REC 230912

__device__ float g_xp[(size_t)2 * MMROWS * NG];
__device__ float g_h[2][2][BB * HH];
__device__ unsigned g_bar_count[2];
__device__ unsigned g_bar_gen[2];

__device__ __forceinline__ float sigmoidf(float x) {
    return 1.0f / (1.0f + __expf(-x));
}
__device__ __forceinline__ uint32_t smem_u32(const void* p) {
    uint32_t a;
    asm("{ .reg .u64 t; cvta.to.shared.u64 t, %1; cvt.u32.u64 %0, t; }" : "=r"(a) : "l"(p));
    return a;
}

__device__ __forceinline__ unsigned bar_arrive(int dir) {
    unsigned gen = *((volatile unsigned*)&g_bar_gen[dir]);
    __threadfence();
    unsigned arr = atomicAdd(&g_bar_count[dir], 1u);
    if (arr == NCTA_DIR - 1) {
        g_bar_count[dir] = 0;
        __threadfence();
        atomicAdd(&g_bar_gen[dir], 1u);
    }
    return gen;
}
__device__ __forceinline__ void bar_wait(int dir, unsigned gen) {
    int spins = 0;
    while (*((volatile unsigned*)&g_bar_gen[dir]) == gen) {
        if (++spins > 64) __nanosleep(20);
    }
    __threadfence();
}

// ---------------------------------------------------------------------------
// xproj (unchanged, known-good)
// ---------------------------------------------------------------------------
__global__ void __launch_bounds__(256) xproj_kernel(
    const float* __restrict__ seq,
    const float* __restrict__ Wfw,
    const float* __restrict__ Wbw)
{
    const int dir = blockIdx.z;
    const float* W = dir ? Wbw : Wfw;
    float* xp = g_xp + (size_t)dir * MMROWS * NG;
    const int m0 = blockIdx.x * 128;
    const int n0 = blockIdx.y * 64;

    __shared__ __align__(16) float As[128][20];
    __shared__ __align__(16) float Bs[16][68];

    const int tid = threadIdx.x;
    const int w = tid >> 5, wm = w & 3, wn = w >> 2;

    wmma::fragment<wmma::accumulator, 16, 16, 8, float> acc[2][2];
#pragma unroll
    for (int i = 0; i < 2; i++)
#pragma unroll
        for (int j = 0; j < 2; j++) wmma::fill_fragment(acc[i][j], 0.0f);

    float ra[8], rb[4];
#pragma unroll
    for (int e = 0; e < 8; e++) {
        int idx = e * 256 + tid; int r = idx >> 4, c = idx & 15;
        ra[e] = seq[(size_t)(m0 + r) * DD + c];
    }
#pragma unroll
    for (int e = 0; e < 4; e++) {
        int idx = e * 256 + tid; int r = idx >> 6, c = idx & 63;
        rb[e] = W[(size_t)r * NG + n0 + c];
    }

    for (int kt = 0; kt < DD / 16; kt++) {
        __syncthreads();
#pragma unroll
        for (int e = 0; e < 8; e++) {
            int idx = e * 256 + tid; int r = idx >> 4, c = idx & 15;
            As[r][c] = ra[e];
        }
#pragma unroll
        for (int e = 0; e < 4; e++) {
            int idx = e * 256 + tid; int r = idx >> 6, c = idx & 63;
            Bs[r][c] = rb[e];
        }
        __syncthreads();
        if (kt + 1 < DD / 16) {
            int k0 = (kt + 1) * 16;
#pragma unroll
            for (int e = 0; e < 8; e++) {
                int idx = e * 256 + tid; int r = idx >> 4, c = idx & 15;
                ra[e] = seq[(size_t)(m0 + r) * DD + k0 + c];
            }
#pragma unroll
            for (int e = 0; e < 4; e++) {
                int idx = e * 256 + tid; int r = idx >> 6, c = idx & 63;
                rb[e] = W[(size_t)(k0 + r) * NG + n0 + c];
            }
        }
#pragma unroll
        for (int k8 = 0; k8 < 16; k8 += 8) {
            wmma::fragment<wmma::matrix_a, 16, 16, 8, wmma::precision::tf32, wmma::row_major> af[2];
            wmma::fragment<wmma::matrix_b, 16, 16, 8, wmma::precision::tf32, wmma::row_major> bf[2];
#pragma unroll
            for (int fm = 0; fm < 2; fm++) {
                wmma::load_matrix_sync(af[fm], &As[wm * 32 + fm * 16][k8], 20);
#pragma unroll
                for (int i = 0; i < af[fm].num_elements; i++)
                    af[fm].x[i] = wmma::__float_to_tf32(af[fm].x[i]);
            }
#pragma unroll
            for (int fn = 0; fn < 2; fn++) {
                wmma::load_matrix_sync(bf[fn], &Bs[k8][wn * 32 + fn * 16], 68);
#pragma unroll
                for (int i = 0; i < bf[fn].num_elements; i++)
                    bf[fn].x[i] = wmma::__float_to_tf32(bf[fn].x[i]);
            }
#pragma unroll
            for (int fm = 0; fm < 2; fm++)
#pragma unroll
                for (int fn = 0; fn < 2; fn++)
                    wmma::mma_sync(acc[fm][fn], af[fm], bf[fn], acc[fm][fn]);
        }
    }
#pragma unroll
    for (int fm = 0; fm < 2; fm++)
#pragma unroll
        for (int fn = 0; fn < 2; fn++) {
            size_t row = m0 + wm * 32 + fm * 16;
            size_t col = n0 + wn * 32 + fn * 16;
            wmma::store_matrix_sync(xp + row * NG + col, acc[fm][fn], NG,
                                    wmma::mem_row_major);
        }
}

__device__ __forceinline__ void cp16s(uint32_t smem_dst, const float* gmem_src) {
    asm volatile("cp.async.ca.shared.global [%0], [%1], 16;\n"
                 :: "r"(smem_dst), "l"(gmem_src));
}

// ---------------------------------------------------------------------------
// Persistent recurrence: 4 compute warps (1/SMSP), each 16m x 64n (4 accs),
// self-staging h via 3-stage single-sync cp.async pipeline on named bar 1.
// A amplification x1, B x4 -> ~1MB/step/SM smem traffic.
// ---------------------------------------------------------------------------
__global__ void __launch_bounds__(512, 1) lstm_persistent(
    const int* __restrict__ seq_len,
    const float* __restrict__ Wfw, const float* __restrict__ bfw,
    const float* __restrict__ Wbw, const float* __restrict__ bbw,
    float* __restrict__ out)
{
    const int dir = blockIdx.x / 48;
    const int jb  = blockIdx.x % 48;
    const float* W    = dir ? Wbw : Wfw;
    const float* bias = dir ? bbw : bfw;
    const float* xp = g_xp + (size_t)dir * MMROWS * NG;

    extern __shared__ __align__(16) char sm[];
    const uint32_t smb = smem_u32(sm);
    float* Ws = (float*)sm;                         // [768][WS_LD]
    float* Gs = (float*)(sm + HS_OFF);              // overlay on stages 0,1
    float* bs = (float*)(sm + TAILOFF);             // 64 floats
    __shared__ unsigned s_gen;

    const int tid = threadIdx.x;
    const int w = tid >> 5;

    // one-time: W slice (tf32-rounded) into Ws
    for (int i = tid; i < 768 * 64; i += 512) {
        int k = i >> 6, n = i & 63;
        int g = n >> 4, c = n & 15;
        Ws[k * WS_LD + n] = wmma::__float_to_tf32(
            W[(size_t)(DD + k) * NG + g * HH + jb * 16 + c]);
    }
    if (tid < 64) {
        int g = tid >> 4, c = tid & 15;
        bs[tid] = bias[g * HH + jb * 16 + c];
    }

    // per-thread cell ownership (update tail, all 512 threads)
    const int j  = tid & 15;
    const int jg = jb * 16 + j;
    const int bb0 = tid >> 4;
    const int bb1 = bb0 + 32;
    const int L0 = seq_len[bb0];
    const int L1 = seq_len[bb1];
    float c0 = 0.f, c1 = 0.f, h0 = 0.f, h1 = 0.f;
    g_h[dir][0][bb0 * HH + jg] = 0.f;
    g_h[dir][0][bb1 * HH + jg] = 0.f;

    // staging mapping (compute warps only, tid 0..127):
    // row = tid>>1 (0..63), half = tid&1; 4 x cp16 per chunk
    const int crow  = (tid & 127) >> 1;
    const int chalf = tid & 1;
    const uint32_t cdst0 = smb + HS_OFF + (uint32_t)(crow * 144 + chalf * 64);
    const int csrc0 = crow * HH + chalf * 16;

    __syncthreads();
    if (tid == 0) { unsigned g0 = bar_arrive(dir); bar_wait(dir, g0); }
    __syncthreads();

    for (int t = 0; t < TT; t++) {
        const int parr = t & 1;
        const float* hsrc = g_h[dir][parr];
        float* hdst = g_h[dir][parr ^ 1];

        const bool a0 = t < L0, a1 = t < L1;
        const int tx0 = dir ? (a0 ? L0 - 1 - t : t) : t;
        const int tx1 = dir ? (a1 ? L1 - 1 - t : t) : t;
        const float* x0 = xp + ((size_t)bb0 * TT + tx0) * NG + jg;
        const float* x1 = xp + ((size_t)bb1 * TT + tx1) * NG + jg;
        float xv00 = x0[0], xv01 = x0[HH], xv02 = x0[2 * HH], xv03 = x0[3 * HH];
        float xv10 = x1[0], xv11 = x1[HH], xv12 = x1[2 * HH], xv13 = x1[3 * HH];

        if (w < 4) {
            wmma::fragment<wmma::accumulator, 16, 16, 8, float> acc[4];
#pragma unroll
            for (int n16 = 0; n16 < 4; n16++) wmma::fill_fragment(acc[n16], 0.f);

            // prologue: issue chunks 0, 1 (stages 0, 1)
#pragma unroll
            for (int i = 0; i < 4; i++)
                cp16s(cdst0 + 0 * STAGE_B + i * 16, hsrc + csrc0 + 0 * 32 + i * 4);
            asm volatile("cp.async.commit_group;\n");
#pragma unroll
            for (int i = 0; i < 4; i++)
                cp16s(cdst0 + 1 * STAGE_B + i * 16, hsrc + csrc0 + 1 * 32 + i * 4);
            asm volatile("cp.async.commit_group;\n");

            for (int ck = 0; ck < 24; ck++) {
                asm volatile("cp.async.wait_group 1;\n");          // chunk ck here
                asm volatile("bar.sync 1, 128;\n" ::: "memory");   // all 4 warps
                if (ck + 2 < 24) {                                  // into (ck-1)'s stage
                    const int st = (ck + 2) % 3;
                    const uint32_t d = cdst0 + (uint32_t)(st * STAGE_B);
                    const float* s = hsrc + csrc0 + (ck + 2) * 32;
#pragma unroll
                    for (int i = 0; i < 4; i++) cp16s(d + i * 16, s + i * 4);
                }
                asm volatile("cp.async.commit_group;\n");

                const float* Hst = (float*)(sm + HS_OFF + (ck % 3) * STAGE_B);
#pragma unroll
                for (int k8 = 0; k8 < 4; k8++) {
                    wmma::fragment<wmma::matrix_a, 16, 16, 8, wmma::precision::tf32, wmma::row_major> af;
                    wmma::load_matrix_sync(af, Hst + (w * 16) * HS_LDW + k8 * 8, HS_LDW);
#pragma unroll
                    for (int n16 = 0; n16 < 4; n16++) {
                        wmma::fragment<wmma::matrix_b, 16, 16, 8, wmma::precision::tf32, wmma::row_major> bf;
                        wmma::load_matrix_sync(bf, Ws + (ck * 32 + k8 * 8) * WS_LD + n16 * 16, WS_LD);
                        wmma::mma_sync(acc[n16], af, bf, acc[n16]);
                    }
                }
            }

            asm volatile("bar.sync 1, 128;\n" ::: "memory");  // all reads done
#pragma unroll
            for (int n16 = 0; n16 < 4; n16++)
                wmma::store_matrix_sync(Gs + (w * 16) * GS_LD + n16 * 16, acc[n16],
                                        GS_LD, wmma::mem_row_major);
        }

        __syncthreads();   // Gs ready for everyone

        float nh0, nh1;
        {
            float gi = Gs[bb0 * GS_LD +  0 + j] + xv00 + bs[j];
            float gj = Gs[bb0 * GS_LD + 16 + j] + xv01 + bs[16 + j];
            float gf = Gs[bb0 * GS_LD + 32 + j] + xv02 + bs[32 + j];
            float go = Gs[bb0 * GS_LD + 48 + j] + xv03 + bs[48 + j];
            float nc = c0 * sigmoidf(gf + 1.f) + sigmoidf(gi) * tanhf(gj);
            nh0 = tanhf(nc) * sigmoidf(go);
            if (a0) { c0 = nc; h0 = nh0; }
            hdst[bb0 * HH + jg] = wmma::__float_to_tf32(h0);
        }
        {
            float gi = Gs[bb1 * GS_LD +  0 + j] + xv10 + bs[j];
            float gj = Gs[bb1 * GS_LD + 16 + j] + xv11 + bs[16 + j];
            float gf = Gs[bb1 * GS_LD + 32 + j] + xv12 + bs[32 + j];
            float go = Gs[bb1 * GS_LD + 48 + j] + xv13 + bs[48 + j];
            float nc = c1 * sigmoidf(gf + 1.f) + sigmoidf(gi) * tanhf(gj);
            nh1 = tanhf(nc) * sigmoidf(go);
            if (a1) { c1 = nc; h1 = nh1; }
            hdst[bb1 * HH + jg] = wmma::__float_to_tf32(h1);
        }

        __syncthreads();                        // Gs reads done; h stores issued
        if (tid == 0) s_gen = bar_arrive(dir);  // fence covers h stores only
        {
            int to0 = (dir && a0) ? (L0 - 1 - t) : t;
            out[((size_t)bb0 * TT + to0) * (2 * HH) + dir * HH + jg] = a0 ? nh0 : 0.f;
            int to1 = (dir && a1) ? (L1 - 1 - t) : t;
            out[((size_t)bb1 * TT + to1) * (2 * HH) + dir * HH + jg] = a1 ? nh1 : 0.f;
        }
        if (tid == 0) bar_wait(dir, s_gen);
        __syncthreads();
    }

    out[(size_t)BB * TT * 2 * HH + (size_t)bb0 * 2 * HH + dir * HH + jg] = h0;
    out[(size_t)BB * TT * 2 * HH + (size_t)bb1 * 2 * HH + dir * HH + jg] = h1;
}

// ---------------------------------------------------------------------------
extern "C" void kernel_launch(void* const* d_in, const int* in_sizes, int n_in,
                              void* d_out, int out_size)
{
    const float* seq     = (const float*)d_in[0];
    const int*   seq_len = (const int*)d_in[1];
    const float* Wfw     = (const float*)d_in[2];
    const float* bfw     = (const float*)d_in[3];
    const float* Wbw     = (const float*)d_in[4];
    const float* bbw     = (const float*)d_in[5];
    float* out = (float*)d_out;

    cudaFuncSetAttribute(lstm_persistent,
                         cudaFuncAttributeMaxDynamicSharedMemorySize, SMEM_REC);

    xproj_kernel<<<dim3(MMROWS / 128, NG / 64, 2), 256>>>(seq, Wfw, Wbw);

    lstm_persistent<<<NCTA, 512, SMEM_REC>>>(seq_len, Wfw, bfw, Wbw, bbw, out);
}

// round 11
// speedup vs baseline: 1.0163x; 1.0163x over previous
#include <cuda_runtime.h>
#include <mma.h>
#include <cstddef>
#include <cstdint>

using namespace nvcuda;

#define BB 64
#define TT 512
#define DD 512
#define HH 768
#define NG 3072
#define MMROWS (BB * TT)
#define NCTA 96
#define NCTA_DIR 48

#define WS_LD 66                 // 768 x 66 floats = 202752 B (fits 3 stages)
#define HS_LD 36                 // stage row: 32 + 4 pad
#define GS_LD 68
#define HS_OFF 202752
#define STAGE_B 9216             // 64 * 36 * 4
#define TAILOFF 230400           // bias
#define SMEM_REC 230912

__device__ float g_xp[(size_t)2 * MMROWS * NG];
__device__ float g_h[2][2][BB * HH];
__device__ unsigned g_bar_count[2];
__device__ unsigned g_bar_gen[2];

__device__ __forceinline__ float sigmoidf(float x) {
    return 1.0f / (1.0f + __expf(-x));
}
__device__ __forceinline__ uint32_t smem_u32(const void* p) {
    uint32_t a;
    asm("{ .reg .u64 t; cvta.to.shared.u64 t, %1; cvt.u32.u64 %0, t; }" : "=r"(a) : "l"(p));
    return a;
}

// split per-direction grid barrier (R7, known-good)
__device__ __forceinline__ unsigned bar_arrive(int dir) {
    unsigned gen = *((volatile unsigned*)&g_bar_gen[dir]);
    __threadfence();
    unsigned arr = atomicAdd(&g_bar_count[dir], 1u);
    if (arr == NCTA_DIR - 1) {
        g_bar_count[dir] = 0;
        __threadfence();
        atomicAdd(&g_bar_gen[dir], 1u);
    }
    return gen;
}
__device__ __forceinline__ void bar_wait(int dir, unsigned gen) {
    int spins = 0;
    while (*((volatile unsigned*)&g_bar_gen[dir]) == gen) {
        if (++spins > 64) __nanosleep(20);
    }
    __threadfence();
}

// ---------------------------------------------------------------------------
// xproj (unchanged, known-good)
// ---------------------------------------------------------------------------
__global__ void __launch_bounds__(256) xproj_kernel(
    const float* __restrict__ seq,
    const float* __restrict__ Wfw,
    const float* __restrict__ Wbw)
{
    const int dir = blockIdx.z;
    const float* W = dir ? Wbw : Wfw;
    float* xp = g_xp + (size_t)dir * MMROWS * NG;
    const int m0 = blockIdx.x * 128;
    const int n0 = blockIdx.y * 64;

    __shared__ __align__(16) float As[128][20];
    __shared__ __align__(16) float Bs[16][68];

    const int tid = threadIdx.x;
    const int w = tid >> 5, wm = w & 3, wn = w >> 2;

    wmma::fragment<wmma::accumulator, 16, 16, 8, float> acc[2][2];
#pragma unroll
    for (int i = 0; i < 2; i++)
#pragma unroll
        for (int j = 0; j < 2; j++) wmma::fill_fragment(acc[i][j], 0.0f);

    float ra[8], rb[4];
#pragma unroll
    for (int e = 0; e < 8; e++) {
        int idx = e * 256 + tid; int r = idx >> 4, c = idx & 15;
        ra[e] = seq[(size_t)(m0 + r) * DD + c];
    }
#pragma unroll
    for (int e = 0; e < 4; e++) {
        int idx = e * 256 + tid; int r = idx >> 6, c = idx & 63;
        rb[e] = W[(size_t)r * NG + n0 + c];
    }

    for (int kt = 0; kt < DD / 16; kt++) {
        __syncthreads();
#pragma unroll
        for (int e = 0; e < 8; e++) {
            int idx = e * 256 + tid; int r = idx >> 4, c = idx & 15;
            As[r][c] = ra[e];
        }
#pragma unroll
        for (int e = 0; e < 4; e++) {
            int idx = e * 256 + tid; int r = idx >> 6, c = idx & 63;
            Bs[r][c] = rb[e];
        }
        __syncthreads();
        if (kt + 1 < DD / 16) {
            int k0 = (kt + 1) * 16;
#pragma unroll
            for (int e = 0; e < 8; e++) {
                int idx = e * 256 + tid; int r = idx >> 4, c = idx & 15;
                ra[e] = seq[(size_t)(m0 + r) * DD + k0 + c];
            }
#pragma unroll
            for (int e = 0; e < 4; e++) {
                int idx = e * 256 + tid; int r = idx >> 6, c = idx & 63;
                rb[e] = W[(size_t)(k0 + r) * NG + n0 + c];
            }
        }
#pragma unroll
        for (int k8 = 0; k8 < 16; k8 += 8) {
            wmma::fragment<wmma::matrix_a, 16, 16, 8, wmma::precision::tf32, wmma::row_major> af[2];
            wmma::fragment<wmma::matrix_b, 16, 16, 8, wmma::precision::tf32, wmma::row_major> bf[2];
#pragma unroll
            for (int fm = 0; fm < 2; fm++) {
                wmma::load_matrix_sync(af[fm], &As[wm * 32 + fm * 16][k8], 20);
#pragma unroll
                for (int i = 0; i < af[fm].num_elements; i++)
                    af[fm].x[i] = wmma::__float_to_tf32(af[fm].x[i]);
            }
#pragma unroll
            for (int fn = 0; fn < 2; fn++) {
                wmma::load_matrix_sync(bf[fn], &Bs[k8][wn * 32 + fn * 16], 68);
#pragma unroll
                for (int i = 0; i < bf[fn].num_elements; i++)
                    bf[fn].x[i] = wmma::__float_to_tf32(bf[fn].x[i]);
            }
#pragma unroll
            for (int fm = 0; fm < 2; fm++)
#pragma unroll
                for (int fn = 0; fn < 2; fn++)
                    wmma::mma_sync(acc[fm][fn], af[fm], bf[fn], acc[fm][fn]);
        }
    }
#pragma unroll
    for (int fm = 0; fm < 2; fm++)
#pragma unroll
        for (int fn = 0; fn < 2; fn++) {
            size_t row = m0 + wm * 32 + fm * 16;
            size_t col = n0 + wn * 32 + fn * 16;
            wmma::store_matrix_sync(xp + row * NG + col, acc[fm][fn], NG,
                                    wmma::mem_row_major);
        }
}

__device__ __forceinline__ void cp16s(uint32_t smem_dst, const float* gmem_src) {
    asm volatile("cp.async.ca.shared.global [%0], [%1], 16;\n"
                 :: "r"(smem_dst), "l"(gmem_src));
}

// ---------------------------------------------------------------------------
// Persistent recurrence: R7 kernel, mainloop = 3-stage SINGLE-sync pipeline.
// 16 warps, 4x4 tiling (known-best). 24 syncthreads/step instead of 48;
// prefetch window 2 chunks.
// ---------------------------------------------------------------------------
__global__ void __launch_bounds__(512, 1) lstm_persistent(
    const int* __restrict__ seq_len,
    const float* __restrict__ Wfw, const float* __restrict__ bfw,
    const float* __restrict__ Wbw, const float* __restrict__ bbw,
    float* __restrict__ out)
{
    const int dir = blockIdx.x / 48;
    const int jb  = blockIdx.x % 48;
    const float* W    = dir ? Wbw : Wfw;
    const float* bias = dir ? bbw : bfw;
    const float* xp = g_xp + (size_t)dir * MMROWS * NG;

    extern __shared__ __align__(16) char sm[];
    const uint32_t smb = smem_u32(sm);
    float* Ws = (float*)sm;                         // [768][WS_LD]
    float* Gs = (float*)(sm + HS_OFF);              // overlay on stages
    float* bs = (float*)(sm + TAILOFF);             // 64 floats
    __shared__ unsigned s_gen;

    const int tid = threadIdx.x;
    const int w  = tid >> 5;
    const int wm = w & 3;      // 16-row (batch) block
    const int wn = w >> 2;     // 16-col (gate) block

    // one-time: W slice (tf32-rounded)
    for (int i = tid; i < 768 * 64; i += 512) {
        int k = i >> 6, n = i & 63;
        int g = n >> 4, c = n & 15;
        Ws[k * WS_LD + n] = wmma::__float_to_tf32(
            W[(size_t)(DD + k) * NG + g * HH + jb * 16 + c]);
    }
    if (tid < 64) {
        int g = tid >> 4, c = tid & 15;
        bs[tid] = bias[g * HH + jb * 16 + c];
    }

    // per-thread cell ownership
    const int j  = tid & 15;
    const int jg = jb * 16 + j;
    const int bb0 = tid >> 4;
    const int bb1 = bb0 + 32;
    const int L0 = seq_len[bb0];
    const int L1 = seq_len[bb1];
    float c0 = 0.f, c1 = 0.f, h0 = 0.f, h1 = 0.f;
    g_h[dir][0][bb0 * HH + jg] = 0.f;
    g_h[dir][0][bb1 * HH + jg] = 0.f;

    // chunk copy mapping: 64 rows x 32 cols, one float4 per thread
    const int cr = tid >> 3;
    const int cc = (tid & 7) * 4;
    const uint32_t cdst = smb + HS_OFF + (uint32_t)(cr * 144 + (tid & 7) * 16);
    const int csrc = cr * HH + cc;

    __syncthreads();
    if (tid == 0) { unsigned g0 = bar_arrive(dir); bar_wait(dir, g0); }
    __syncthreads();

    for (int t = 0; t < TT; t++) {
        const int parr = t & 1;
        const float* hsrc = g_h[dir][parr];
        float* hdst = g_h[dir][parr ^ 1];

        const bool a0 = t < L0, a1 = t < L1;
        const int tx0 = dir ? (a0 ? L0 - 1 - t : t) : t;
        const int tx1 = dir ? (a1 ? L1 - 1 - t : t) : t;
        const float* x0 = xp + ((size_t)bb0 * TT + tx0) * NG + jg;
        const float* x1 = xp + ((size_t)bb1 * TT + tx1) * NG + jg;
        float xv00 = x0[0], xv01 = x0[HH], xv02 = x0[2 * HH], xv03 = x0[3 * HH];
        float xv10 = x1[0], xv11 = x1[HH], xv12 = x1[2 * HH], xv13 = x1[3 * HH];

        wmma::fragment<wmma::accumulator, 16, 16, 8, float> acc;
        wmma::fill_fragment(acc, 0.f);

        // prologue: issue chunks 0, 1 (stages 0, 1)
        cp16s(cdst + 0 * STAGE_B, hsrc + csrc + 0);
        asm volatile("cp.async.commit_group;\n");
        cp16s(cdst + 1 * STAGE_B, hsrc + csrc + 32);
        asm volatile("cp.async.commit_group;\n");

        // 3-stage, ONE syncthreads per chunk
        for (int ck = 0; ck < 24; ck++) {
            if (ck < 23) asm volatile("cp.async.wait_group 1;\n");
            else         asm volatile("cp.async.wait_group 0;\n");
            __syncthreads();   // chunk ck visible to all; readers of ck-1 done

            if (ck + 2 < 24) { // issue ck+2 into stage (ck+2)%3 == (ck-1)%3
                cp16s(cdst + (uint32_t)(((ck + 2) % 3) * STAGE_B),
                      hsrc + csrc + (ck + 2) * 32);
            }
            asm volatile("cp.async.commit_group;\n");  // commit even if empty

            const float* Hst = (float*)(sm + HS_OFF + (ck % 3) * STAGE_B);
#pragma unroll
            for (int k8 = 0; k8 < 4; k8++) {
                wmma::fragment<wmma::matrix_a, 16, 16, 8, wmma::precision::tf32, wmma::row_major> af;
                wmma::load_matrix_sync(af, Hst + (wm * 16) * HS_LD + k8 * 8, HS_LD);
                wmma::fragment<wmma::matrix_b, 16, 16, 8, wmma::precision::tf32, wmma::row_major> bf;
                wmma::load_matrix_sync(bf, Ws + (ck * 32 + k8 * 8) * WS_LD + wn * 16, WS_LD);
                wmma::mma_sync(acc, af, bf, acc);
            }
        }

        __syncthreads();   // all fragment reads done; overlay Gs on stages
        wmma::store_matrix_sync(Gs + (wm * 16) * GS_LD + wn * 16, acc, GS_LD,
                                wmma::mem_row_major);
        __syncthreads();

        // fused cell update; h stores before the arrive fence
        float nh0, nh1;
        {
            float gi = Gs[bb0 * GS_LD +  0 + j] + xv00 + bs[j];
            float gj = Gs[bb0 * GS_LD + 16 + j] + xv01 + bs[16 + j];
            float gf = Gs[bb0 * GS_LD + 32 + j] + xv02 + bs[32 + j];
            float go = Gs[bb0 * GS_LD + 48 + j] + xv03 + bs[48 + j];
            float nc = c0 * sigmoidf(gf + 1.f) + sigmoidf(gi) * tanhf(gj);
            nh0 = tanhf(nc) * sigmoidf(go);
            if (a0) { c0 = nc; h0 = nh0; }
            hdst[bb0 * HH + jg] = wmma::__float_to_tf32(h0);
        }
        {
            float gi = Gs[bb1 * GS_LD +  0 + j] + xv10 + bs[j];
            float gj = Gs[bb1 * GS_LD + 16 + j] + xv11 + bs[16 + j];
            float gf = Gs[bb1 * GS_LD + 32 + j] + xv12 + bs[32 + j];
            float go = Gs[bb1 * GS_LD + 48 + j] + xv13 + bs[48 + j];
            float nc = c1 * sigmoidf(gf + 1.f) + sigmoidf(gi) * tanhf(gj);
            nh1 = tanhf(nc) * sigmoidf(go);
            if (a1) { c1 = nc; h1 = nh1; }
            hdst[bb1 * HH + jg] = wmma::__float_to_tf32(h1);
        }

        __syncthreads();
        if (tid == 0) s_gen = bar_arrive(dir);   // fence covers h stores only
        {
            int to0 = (dir && a0) ? (L0 - 1 - t) : t;
            out[((size_t)bb0 * TT + to0) * (2 * HH) + dir * HH + jg] = a0 ? nh0 : 0.f;
            int to1 = (dir && a1) ? (L1 - 1 - t) : t;
            out[((size_t)bb1 * TT + to1) * (2 * HH) + dir * HH + jg] = a1 ? nh1 : 0.f;
        }
        if (tid == 0) bar_wait(dir, s_gen);
        __syncthreads();
    }

    out[(size_t)BB * TT * 2 * HH + (size_t)bb0 * 2 * HH + dir * HH + jg] = h0;
    out[(size_t)BB * TT * 2 * HH + (size_t)bb1 * 2 * HH + dir * HH + jg] = h1;
}

// ---------------------------------------------------------------------------
extern "C" void kernel_launch(void* const* d_in, const int* in_sizes, int n_in,
                              void* d_out, int out_size)
{
    const float* seq     = (const float*)d_in[0];
    const int*   seq_len = (const int*)d_in[1];
    const float* Wfw     = (const float*)d_in[2];
    const float* bfw     = (const float*)d_in[3];
    const float* Wbw     = (const float*)d_in[4];
    const float* bbw     = (const float*)d_in[5];
    float* out = (float*)d_out;

    cudaFuncSetAttribute(lstm_persistent,
                         cudaFuncAttributeMaxDynamicSharedMemorySize, SMEM_REC);

    xproj_kernel<<<dim3(MMROWS / 128, NG / 64, 2), 256>>>(seq, Wfw, Wbw);

    lstm_persistent<<<NCTA, 512, SMEM_REC>>>(seq_len, Wfw, bfw, Wbw, bbw, out);
}

// round 12
// speedup vs baseline: 1.9372x; 1.9062x over previous
#include <cuda_runtime.h>
#include <cuda_fp16.h>
#include <mma.h>
#include <cstddef>
#include <cstdint>

using namespace nvcuda;

#define BB 64
#define TT 512
#define DD 512
#define HH 768
#define NG 3072
#define MMROWS (BB * TT)
#define NCTA 96
#define NCTA_DIR 48

// recurrence smem layout (bytes); all fp16 leading dims = 80 halves (160B rows)
#define LDH 80
#define ST_OFF 122880            // Ws: 768 x 80 halves = 122880 B
#define ST_B 10240               // stage: 64 x 80 halves
#define NSTAGE 4
#define GS_OFF 163840            // Gs: 64 x 68 fp32 = 17408 B
#define GS_LD 68
#define BS_OFF 181248
#define SMEM_REC 181504

__device__ float  g_xp[(size_t)2 * MMROWS * NG];
__device__ __half g_h[2][2][BB * HH];
__device__ unsigned g_bar_count[2];
__device__ unsigned g_bar_gen[2];

__device__ __forceinline__ float sigmoidf(float x) {
    return 1.0f / (1.0f + __expf(-x));
}
__device__ __forceinline__ uint32_t smem_u32(const void* p) {
    uint32_t a;
    asm("{ .reg .u64 t; cvta.to.shared.u64 t, %1; cvt.u32.u64 %0, t; }" : "=r"(a) : "l"(p));
    return a;
}

// split per-direction grid barrier (R7, known-good)
__device__ __forceinline__ unsigned bar_arrive(int dir) {
    unsigned gen = *((volatile unsigned*)&g_bar_gen[dir]);
    __threadfence();
    unsigned arr = atomicAdd(&g_bar_count[dir], 1u);
    if (arr == NCTA_DIR - 1) {
        g_bar_count[dir] = 0;
        __threadfence();
        atomicAdd(&g_bar_gen[dir], 1u);
    }
    return gen;
}
__device__ __forceinline__ void bar_wait(int dir, unsigned gen) {
    int spins = 0;
    while (*((volatile unsigned*)&g_bar_gen[dir]) == gen) {
        if (++spins > 64) __nanosleep(20);
    }
    __threadfence();
}

// ---------------------------------------------------------------------------
// xproj (unchanged, known-good)
// ---------------------------------------------------------------------------
__global__ void __launch_bounds__(256) xproj_kernel(
    const float* __restrict__ seq,
    const float* __restrict__ Wfw,
    const float* __restrict__ Wbw)
{
    const int dir = blockIdx.z;
    const float* W = dir ? Wbw : Wfw;
    float* xp = g_xp + (size_t)dir * MMROWS * NG;
    const int m0 = blockIdx.x * 128;
    const int n0 = blockIdx.y * 64;

    __shared__ __align__(16) float As[128][20];
    __shared__ __align__(16) float Bs[16][68];

    const int tid = threadIdx.x;
    const int w = tid >> 5, wm = w & 3, wn = w >> 2;

    wmma::fragment<wmma::accumulator, 16, 16, 8, float> acc[2][2];
#pragma unroll
    for (int i = 0; i < 2; i++)
#pragma unroll
        for (int j = 0; j < 2; j++) wmma::fill_fragment(acc[i][j], 0.0f);

    float ra[8], rb[4];
#pragma unroll
    for (int e = 0; e < 8; e++) {
        int idx = e * 256 + tid; int r = idx >> 4, c = idx & 15;
        ra[e] = seq[(size_t)(m0 + r) * DD + c];
    }
#pragma unroll
    for (int e = 0; e < 4; e++) {
        int idx = e * 256 + tid; int r = idx >> 6, c = idx & 63;
        rb[e] = W[(size_t)r * NG + n0 + c];
    }

    for (int kt = 0; kt < DD / 16; kt++) {
        __syncthreads();
#pragma unroll
        for (int e = 0; e < 8; e++) {
            int idx = e * 256 + tid; int r = idx >> 4, c = idx & 15;
            As[r][c] = ra[e];
        }
#pragma unroll
        for (int e = 0; e < 4; e++) {
            int idx = e * 256 + tid; int r = idx >> 6, c = idx & 63;
            Bs[r][c] = rb[e];
        }
        __syncthreads();
        if (kt + 1 < DD / 16) {
            int k0 = (kt + 1) * 16;
#pragma unroll
            for (int e = 0; e < 8; e++) {
                int idx = e * 256 + tid; int r = idx >> 4, c = idx & 15;
                ra[e] = seq[(size_t)(m0 + r) * DD + k0 + c];
            }
#pragma unroll
            for (int e = 0; e < 4; e++) {
                int idx = e * 256 + tid; int r = idx >> 6, c = idx & 63;
                rb[e] = W[(size_t)(k0 + r) * NG + n0 + c];
            }
        }
#pragma unroll
        for (int k8 = 0; k8 < 16; k8 += 8) {
            wmma::fragment<wmma::matrix_a, 16, 16, 8, wmma::precision::tf32, wmma::row_major> af[2];
            wmma::fragment<wmma::matrix_b, 16, 16, 8, wmma::precision::tf32, wmma::row_major> bf[2];
#pragma unroll
            for (int fm = 0; fm < 2; fm++) {
                wmma::load_matrix_sync(af[fm], &As[wm * 32 + fm * 16][k8], 20);
#pragma unroll
                for (int i = 0; i < af[fm].num_elements; i++)
                    af[fm].x[i] = wmma::__float_to_tf32(af[fm].x[i]);
            }
#pragma unroll
            for (int fn = 0; fn < 2; fn++) {
                wmma::load_matrix_sync(bf[fn], &Bs[k8][wn * 32 + fn * 16], 68);
#pragma unroll
                for (int i = 0; i < bf[fn].num_elements; i++)
                    bf[fn].x[i] = wmma::__float_to_tf32(bf[fn].x[i]);
            }
#pragma unroll
            for (int fm = 0; fm < 2; fm++)
#pragma unroll
                for (int fn = 0; fn < 2; fn++)
                    wmma::mma_sync(acc[fm][fn], af[fm], bf[fn], acc[fm][fn]);
        }
    }
#pragma unroll
    for (int fm = 0; fm < 2; fm++)
#pragma unroll
        for (int fn = 0; fn < 2; fn++) {
            size_t row = m0 + wm * 32 + fm * 16;
            size_t col = n0 + wn * 32 + fn * 16;
            wmma::store_matrix_sync(xp + row * NG + col, acc[fm][fn], NG,
                                    wmma::mem_row_major);
        }
}

__device__ __forceinline__ void cp16s(uint32_t smem_dst, const void* gmem_src) {
    asm volatile("cp.async.ca.shared.global [%0], [%1], 16;\n"
                 :: "r"(smem_dst), "l"(gmem_src));
}

// ---------------------------------------------------------------------------
// Persistent recurrence: fp16 WMMA (m16n16k16), chunk K=64, 12 iters/step,
// 4 stages / prefetch depth 3, dual-sync per chunk, 4x4 warp tiling.
// h stored fp16 in gmem; W slice fp16 resident in smem; fp32 update tail.
// ---------------------------------------------------------------------------
__global__ void __launch_bounds__(512, 1) lstm_persistent(
    const int* __restrict__ seq_len,
    const float* __restrict__ Wfw, const float* __restrict__ bfw,
    const float* __restrict__ Wbw, const float* __restrict__ bbw,
    float* __restrict__ out)
{
    const int dir = blockIdx.x / 48;
    const int jb  = blockIdx.x % 48;
    const float* W    = dir ? Wbw : Wfw;
    const float* bias = dir ? bbw : bfw;
    const float* xp = g_xp + (size_t)dir * MMROWS * NG;

    extern __shared__ __align__(128) char sm[];
    const uint32_t smb = smem_u32(sm);
    __half* Ws = (__half*)sm;                       // [768][LDH]
    float*  Gs = (float*)(sm + GS_OFF);             // [64][GS_LD]
    float*  bs = (float*)(sm + BS_OFF);             // 64 floats
    __shared__ unsigned s_gen;

    const int tid = threadIdx.x;
    const int w  = tid >> 5;
    const int wm = w & 3;      // 16-row (batch) block
    const int wn = w >> 2;     // 16-col (gate) block

    // one-time: W slice -> fp16 smem
    for (int i = tid; i < 768 * 64; i += 512) {
        int k = i >> 6, n = i & 63;
        int g = n >> 4, c = n & 15;
        Ws[k * LDH + n] = __float2half(W[(size_t)(DD + k) * NG + g * HH + jb * 16 + c]);
    }
    if (tid < 64) {
        int g = tid >> 4, c = tid & 15;
        bs[tid] = bias[g * HH + jb * 16 + c];
    }

    // per-thread cell ownership
    const int j  = tid & 15;
    const int jg = jb * 16 + j;
    const int bb0 = tid >> 4;
    const int bb1 = bb0 + 32;
    const int L0 = seq_len[bb0];
    const int L1 = seq_len[bb1];
    float c0 = 0.f, c1 = 0.f, h0 = 0.f, h1 = 0.f;
    g_h[dir][0][bb0 * HH + jg] = __float2half(0.f);
    g_h[dir][0][bb1 * HH + jg] = __float2half(0.f);

    // chunk copy mapping: 64 rows x 64 halves (128B/row) = 512 x 16B
    const int cr = tid >> 3;          // row 0..63
    const int cu = tid & 7;           // 16B unit 0..7
    const uint32_t cdst = smb + ST_OFF + (uint32_t)(cr * (LDH * 2) + cu * 16);
    const int csrc = cr * HH + cu * 8;   // halves

    __syncthreads();
    if (tid == 0) { unsigned g0 = bar_arrive(dir); bar_wait(dir, g0); }
    __syncthreads();

    for (int t = 0; t < TT; t++) {
        const int parr = t & 1;
        const __half* hsrc = g_h[dir][parr];
        __half* hdst = g_h[dir][parr ^ 1];

        const bool a0 = t < L0, a1 = t < L1;
        const int tx0 = dir ? (a0 ? L0 - 1 - t : t) : t;
        const int tx1 = dir ? (a1 ? L1 - 1 - t : t) : t;
        const float* x0 = xp + ((size_t)bb0 * TT + tx0) * NG + jg;
        const float* x1 = xp + ((size_t)bb1 * TT + tx1) * NG + jg;
        float xv00 = x0[0], xv01 = x0[HH], xv02 = x0[2 * HH], xv03 = x0[3 * HH];
        float xv10 = x1[0], xv11 = x1[HH], xv12 = x1[2 * HH], xv13 = x1[3 * HH];

        wmma::fragment<wmma::accumulator, 16, 16, 16, float> acc;
        wmma::fill_fragment(acc, 0.f);

        // prologue: issue chunks 0..3 into stages 0..3
#pragma unroll
        for (int s = 0; s < NSTAGE; s++) {
            cp16s(cdst + s * ST_B, hsrc + csrc + s * 64);
            asm volatile("cp.async.commit_group;\n");
        }

        for (int ck = 0; ck < 12; ck++) {
            if (ck < 9)       asm volatile("cp.async.wait_group 3;\n");
            else if (ck == 9) asm volatile("cp.async.wait_group 2;\n");
            else if (ck == 10)asm volatile("cp.async.wait_group 1;\n");
            else              asm volatile("cp.async.wait_group 0;\n");
            __syncthreads();   // chunk ck visible to all warps

            const __half* Hst = (const __half*)(sm + ST_OFF + (ck & 3) * ST_B);
#pragma unroll
            for (int k16 = 0; k16 < 4; k16++) {
                wmma::fragment<wmma::matrix_a, 16, 16, 16, half, wmma::row_major> af;
                wmma::load_matrix_sync(af, Hst + (wm * 16) * LDH + k16 * 16, LDH);
                wmma::fragment<wmma::matrix_b, 16, 16, 16, half, wmma::row_major> bf;
                wmma::load_matrix_sync(bf, Ws + (ck * 64 + k16 * 16) * LDH + wn * 16, LDH);
                wmma::mma_sync(acc, af, bf, acc);
            }
            __syncthreads();   // readers of stage ck&3 done

            if (ck + 4 < 12) { // refill the just-consumed stage
                cp16s(cdst + (ck & 3) * ST_B, hsrc + csrc + (ck + 4) * 64);
                asm volatile("cp.async.commit_group;\n");
            }
        }

        // stage gates (Gs is its own region; no overlay hazard)
        wmma::store_matrix_sync(Gs + (wm * 16) * GS_LD + wn * 16, acc, GS_LD,
                                wmma::mem_row_major);
        __syncthreads();

        // fused cell update (fp32); h stored fp16 before the arrive fence
        float nh0, nh1;
        {
            float gi = Gs[bb0 * GS_LD +  0 + j] + xv00 + bs[j];
            float gj = Gs[bb0 * GS_LD + 16 + j] + xv01 + bs[16 + j];
            float gf = Gs[bb0 * GS_LD + 32 + j] + xv02 + bs[32 + j];
            float go = Gs[bb0 * GS_LD + 48 + j] + xv03 + bs[48 + j];
            float nc = c0 * sigmoidf(gf + 1.f) + sigmoidf(gi) * tanhf(gj);
            nh0 = tanhf(nc) * sigmoidf(go);
            if (a0) { c0 = nc; h0 = nh0; }
            hdst[bb0 * HH + jg] = __float2half(h0);
        }
        {
            float gi = Gs[bb1 * GS_LD +  0 + j] + xv10 + bs[j];
            float gj = Gs[bb1 * GS_LD + 16 + j] + xv11 + bs[16 + j];
            float gf = Gs[bb1 * GS_LD + 32 + j] + xv12 + bs[32 + j];
            float go = Gs[bb1 * GS_LD + 48 + j] + xv13 + bs[48 + j];
            float nc = c1 * sigmoidf(gf + 1.f) + sigmoidf(gi) * tanhf(gj);
            nh1 = tanhf(nc) * sigmoidf(go);
            if (a1) { c1 = nc; h1 = nh1; }
            hdst[bb1 * HH + jg] = __float2half(h1);
        }

        __syncthreads();
        if (tid == 0) s_gen = bar_arrive(dir);   // fence covers h stores only
        {
            int to0 = (dir && a0) ? (L0 - 1 - t) : t;
            out[((size_t)bb0 * TT + to0) * (2 * HH) + dir * HH + jg] = a0 ? nh0 : 0.f;
            int to1 = (dir && a1) ? (L1 - 1 - t) : t;
            out[((size_t)bb1 * TT + to1) * (2 * HH) + dir * HH + jg] = a1 ? nh1 : 0.f;
        }
        if (tid == 0) bar_wait(dir, s_gen);
        __syncthreads();
    }

    out[(size_t)BB * TT * 2 * HH + (size_t)bb0 * 2 * HH + dir * HH + jg] = h0;
    out[(size_t)BB * TT * 2 * HH + (size_t)bb1 * 2 * HH + dir * HH + jg] = h1;
}

// ---------------------------------------------------------------------------
extern "C" void kernel_launch(void* const* d_in, const int* in_sizes, int n_in,
                              void* d_out, int out_size)
{
    const float* seq     = (const float*)d_in[0];
    const int*   seq_len = (const int*)d_in[1];
    const float* Wfw     = (const float*)d_in[2];
    const float* bfw     = (const float*)d_in[3];
    const float* Wbw     = (const float*)d_in[4];
    const float* bbw     = (const float*)d_in[5];
    float* out = (float*)d_out;

    cudaFuncSetAttribute(lstm_persistent,
                         cudaFuncAttributeMaxDynamicSharedMemorySize, SMEM_REC);

    xproj_kernel<<<dim3(MMROWS / 128, NG / 64, 2), 256>>>(seq, Wfw, Wbw);

    lstm_persistent<<<NCTA, 512, SMEM_REC>>>(seq_len, Wfw, bfw, Wbw, bbw, out);
}